// round 12
// baseline (speedup 1.0000x reference)
#include <cuda_runtime.h>
#include <math.h>

// Fixed problem shapes
#define DIM    32
#define NN     32          // neighbors per entity
#define NRELS  64
#define RP     33          // padded pitch for rel table in smem
#define TPB    256         // 8 warps; each warp does 4 hop-1 nodes sequentially
#define NWARP  8
#define FULL   0xffffffffu

__device__ __forceinline__ float wmax(float v) {
#pragma unroll
    for (int o = 16; o; o >>= 1) v = fmaxf(v, __shfl_xor_sync(FULL, v, o));
    return v;
}
__device__ __forceinline__ float wsum(float v) {
#pragma unroll
    for (int o = 16; o; o >>= 1) v += __shfl_xor_sync(FULL, v, o);
    return v;
}

// One attention-aggregate-linear node update. Broadcasts via shuffle (ALU
// pipe) instead of smem staging (LSU pipe). No smem staging arrays at all.
//   sv : lane = feature d  (self vector)
//   en : lane = neighbor n (neighbor entity id; unused when FROM_SMEM)
//   rr : lane = neighbor n (relation id)
// Returns pre-activation o for output feature = lane.
template <bool FROM_SMEM>
__device__ __forceinline__ float node_update(float sv, int en, int rr,
                                             const float* __restrict__ rel_s,
                                             const float* __restrict__ W_s,
                                             const float* __restrict__ b_s,
                                             const float* __restrict__ src,
                                             int lane)
{
    // --- attention score: s = dot(self, rel[rr]), lane = neighbor n ---
    const float* rp = &rel_s[rr * RP];
    float s = 0.f;
#pragma unroll
    for (int d = 0; d < DIM; d++)
        s += __shfl_sync(FULL, sv, d) * rp[d];

    // --- softmax over the 32 neighbors ---
    const float mx = wmax(s);
    const float ex = __expf(s - mx);
    const float sc = ex / wsum(ex);

    // --- weighted aggregate of neighbor vectors; lane = feature d ---
    float a = 0.f;
#pragma unroll
    for (int n = 0; n < NN; n++) {
        const float w_ = __shfl_sync(FULL, sc, n);
        if (FROM_SMEM) {
            a += w_ * src[n * DIM + lane];                  // coalesced LDS
        } else {
            const int e = __shfl_sync(FULL, en, n);
            a += w_ * src[e * DIM + lane];                  // one 128B row LDG
        }
    }
    const float h = sv + a;

    // --- GEMV: o[lane] = b[lane] + sum_d h[d] * W[d][lane] ---
    float o = b_s[lane];
#pragma unroll
    for (int d = 0; d < DIM; d++)
        o += __shfl_sync(FULL, h, d) * W_s[d * DIM + lane]; // coalesced LDS
    return o;
}

// ---------------------------------------------------------------------------
// Fused KGCN: one block (8 warps) per batch element.
//   Phase A: warp w handles hop-1 nodes m = w + 8k (k=0..3) -> out1 (smem);
//            warp 0 then computes hop-0 v0 (kept in registers).
//   Phase B: warp 0 runs iteration 1 over out1 -> final output.
// No prefetch pipeline: minimal live state to keep registers low (R8 lesson).
// ---------------------------------------------------------------------------
__global__ __launch_bounds__(TPB)
void kgcn_fused_kernel(const int* __restrict__ drug,
                       const int* __restrict__ adj_e,
                       const int* __restrict__ adj_r,
                       const float* __restrict__ ent,
                       const float* __restrict__ rel,
                       const float* __restrict__ W,
                       const float* __restrict__ bias,
                       float* __restrict__ out)
{
    __shared__ float rel_s[NRELS * RP];     // 8448 B
    __shared__ float W_s[DIM * DIM];        // 4096 B  W_s[d][j]
    __shared__ float b_s[DIM];
    __shared__ float out1[NN * DIM];        // hop-1 results, 4096 B

    const int tid  = threadIdx.x;
    const int lane = tid & 31;
    const int w    = tid >> 5;

    for (int i = tid; i < NRELS * DIM; i += TPB)
        rel_s[(i >> 5) * RP + (i & 31)] = rel[i];
    for (int i = tid; i < DIM * DIM; i += TPB) W_s[i] = W[i];
    if (tid < DIM) b_s[tid] = bias[tid];
    __syncthreads();

    const int b  = blockIdx.x;
    const int e0 = drug[b];

    // ---- Phase A: 4 hop-1 nodes per warp, sequential (no prefetch) ----
#pragma unroll
    for (int k = 0; k < 4; k++) {
        const int m  = w + k * NWARP;
        const int e1 = adj_e[e0 * NN + m];
        const float sv = ent[e1 * DIM + lane];     // coalesced row
        const int   en = adj_e[e1 * NN + lane];    // lane = neighbor n
        const int   rr = adj_r[e1 * NN + lane];

        const float o = node_update<false>(sv, en, rr, rel_s, W_s, b_s, ent, lane);
        out1[m * DIM + lane] = 1.f / (1.f + __expf(-o));   // sigmoid
    }

    // ---- hop-0 (warp 0): v0 kept in registers across the barrier ----
    float v0 = 0.f;
    int rr0 = 0;
    if (w == 0) {
        const float sv = ent[e0 * DIM + lane];
        const int   en = adj_e[e0 * NN + lane];
        rr0 = adj_r[e0 * NN + lane];

        const float o = node_update<false>(sv, en, rr0, rel_s, W_s, b_s, ent, lane);
        v0 = 1.f / (1.f + __expf(-o));
    }

    __syncthreads();

    // ---- Phase B: iteration 1 (warp 0), neighbors = out1 in smem ----
    if (w == 0) {
        const float o = node_update<true>(v0, 0, rr0, rel_s, W_s, b_s, out1, lane);
        out[b * DIM + lane] = tanhf(o);
    }
}

extern "C" void kernel_launch(void* const* d_in, const int* in_sizes, int n_in,
                              void* d_out, int out_size)
{
    const int*   drug  = (const int*)  d_in[0];  // [B]
    const int*   adj_e = (const int*)  d_in[1];  // [NUM_ENT, 32]
    const int*   adj_r = (const int*)  d_in[2];  // [NUM_ENT, 32]
    const float* ent   = (const float*)d_in[3];  // [NUM_ENT, 32]
    const float* rel   = (const float*)d_in[4];  // [64, 32]
    const float* W     = (const float*)d_in[5];  // [32, 32]
    const float* bias  = (const float*)d_in[6];  // [32]
    float* out = (float*)d_out;

    const int B = in_sizes[0];
    kgcn_fused_kernel<<<B, TPB>>>(drug, adj_e, adj_r, ent, rel, W, bias, out);
}

// round 13
// speedup vs baseline: 1.5061x; 1.5061x over previous
#include <cuda_runtime.h>
#include <math.h>

// Fixed problem shapes
#define DIM    32
#define NN     32          // neighbors per entity
#define NRELS  64
#define RP     33          // padded pitch for rel table in smem
#define TPB    256         // 8 warps/block, 8 blocks/SM, 1024 blocks = 1 wave
#define NWARP  8

__device__ __forceinline__ float wmax(float v) {
#pragma unroll
    for (int o = 16; o; o >>= 1) v = fmaxf(v, __shfl_xor_sync(0xffffffffu, v, o));
    return v;
}
__device__ __forceinline__ float wsum(float v) {
#pragma unroll
    for (int o = 16; o; o >>= 1) v += __shfl_xor_sync(0xffffffffu, v, o);
    return v;
}

// ---------------------------------------------------------------------------
// Fused KGCN, R6-proven node body (scalar smem staging) in a 1-wave shape:
// one block (8 warps) per batch element, warp w does hop-1 nodes w+8k,
// warp 7 additionally does hop-0, warp 0 does the final iteration-1 step.
// ---------------------------------------------------------------------------
__global__ __launch_bounds__(TPB)
void kgcn_fused_kernel(const int* __restrict__ drug,
                       const int* __restrict__ adj_e,
                       const int* __restrict__ adj_r,
                       const float* __restrict__ ent,
                       const float* __restrict__ rel,
                       const float* __restrict__ W,
                       const float* __restrict__ bias,
                       float* __restrict__ out)
{
    __shared__ float rel_s[NRELS * RP];     // 8448 B
    __shared__ float W_s[DIM * DIM];        // 4096 B  W_s[d][j]
    __shared__ float b_s[DIM];
    __shared__ float out1[NN * DIM];        // hop-1 results, 4096 B
    __shared__ float v0_s[DIM];
    __shared__ float sv_s[NWARP][32];       // per-warp staging
    __shared__ float sc_s[NWARP][32];
    __shared__ int   en_s[NWARP][32];

    const int tid  = threadIdx.x;
    const int lane = tid & 31;
    const int w    = tid >> 5;

    for (int i = tid; i < NRELS * DIM; i += TPB)
        rel_s[(i >> 5) * RP + (i & 31)] = rel[i];
    for (int i = tid; i < DIM * DIM; i += TPB) W_s[i] = W[i];
    if (tid < DIM) b_s[tid] = bias[tid];
    __syncthreads();

    const int b  = blockIdx.x;
    const int e0 = drug[b];

    float* svb = sv_s[w];
    float* scb = sc_s[w];
    int*   enb = en_s[w];

    // ---------------- Phase A: 4 hop-1 nodes per warp ----------------
#pragma unroll
    for (int k = 0; k < 4; k++) {
        const int m  = w + k * NWARP;
        const int e1 = adj_e[e0 * NN + m];

        const float sv = ent[e1 * DIM + lane];       // coalesced row
        const int   en = adj_e[e1 * NN + lane];      // lane = neighbor n
        const int   rr = adj_r[e1 * NN + lane];

        __syncwarp();
        svb[lane] = sv;
        enb[lane] = en;
        __syncwarp();

        // attention score for neighbor n = lane
        float s = 0.f;
#pragma unroll
        for (int d = 0; d < DIM; d++) s += svb[d] * rel_s[rr * RP + d];

        const float mx = wmax(s);
        const float ex = __expf(s - mx);
        const float sm = wsum(ex);
        scb[lane] = ex / sm;
        __syncwarp();

        // weighted aggregate of neighbor embeddings; lane = feature dim
        float a = 0.f;
#pragma unroll
        for (int n = 0; n < NN; n++)
            a += scb[n] * ent[enb[n] * DIM + lane];

        const float h = sv + a;
        __syncwarp();
        svb[lane] = h;
        __syncwarp();

        float o = b_s[lane];
#pragma unroll
        for (int d = 0; d < DIM; d++) o += svb[d] * W_s[d * DIM + lane];

        out1[m * DIM + lane] = 1.f / (1.f + __expf(-o));   // sigmoid
    }

    // ---- hop-0 on warp 7 (runs while warps 0-6 are already done) ----
    if (w == NWARP - 1) {
        const float sv = ent[e0 * DIM + lane];
        const int   en = adj_e[e0 * NN + lane];
        const int   rr = adj_r[e0 * NN + lane];

        __syncwarp();
        svb[lane] = sv;
        enb[lane] = en;
        __syncwarp();

        float s = 0.f;
#pragma unroll
        for (int d = 0; d < DIM; d++) s += svb[d] * rel_s[rr * RP + d];

        const float mx = wmax(s);
        const float ex = __expf(s - mx);
        const float sm = wsum(ex);
        scb[lane] = ex / sm;
        __syncwarp();

        float a = 0.f;
#pragma unroll
        for (int n = 0; n < NN; n++)
            a += scb[n] * ent[enb[n] * DIM + lane];

        const float h = sv + a;
        __syncwarp();
        svb[lane] = h;
        __syncwarp();

        float o = b_s[lane];
#pragma unroll
        for (int d = 0; d < DIM; d++) o += svb[d] * W_s[d * DIM + lane];

        v0_s[lane] = 1.f / (1.f + __expf(-o));
    }

    __syncthreads();

    // ---------------- Phase B: iteration 1 (warp 0) ----------------
    if (w == 0) {
        const float v0 = v0_s[lane];
        const int   rr = adj_r[e0 * NN + lane];      // same relation rows as hop-0

        __syncwarp();
        svb[lane] = v0;
        __syncwarp();

        float s = 0.f;
#pragma unroll
        for (int d = 0; d < DIM; d++) s += svb[d] * rel_s[rr * RP + d];

        const float mx = wmax(s);
        const float ex = __expf(s - mx);
        const float sm = wsum(ex);
        scb[lane] = ex / sm;
        __syncwarp();

        // neighbors are the hop-1 outputs in shared memory (coalesced LDS)
        float a = 0.f;
#pragma unroll
        for (int n = 0; n < NN; n++)
            a += scb[n] * out1[n * DIM + lane];

        const float h = v0 + a;
        __syncwarp();
        svb[lane] = h;
        __syncwarp();

        float o = b_s[lane];
#pragma unroll
        for (int d = 0; d < DIM; d++) o += svb[d] * W_s[d * DIM + lane];

        out[b * DIM + lane] = tanhf(o);
    }
}

extern "C" void kernel_launch(void* const* d_in, const int* in_sizes, int n_in,
                              void* d_out, int out_size)
{
    const int*   drug  = (const int*)  d_in[0];  // [B]
    const int*   adj_e = (const int*)  d_in[1];  // [NUM_ENT, 32]
    const int*   adj_r = (const int*)  d_in[2];  // [NUM_ENT, 32]
    const float* ent   = (const float*)d_in[3];  // [NUM_ENT, 32]
    const float* rel   = (const float*)d_in[4];  // [64, 32]
    const float* W     = (const float*)d_in[5];  // [32, 32]
    const float* bias  = (const float*)d_in[6];  // [32]
    float* out = (float*)d_out;

    const int B = in_sizes[0];
    kgcn_fused_kernel<<<B, TPB>>>(drug, adj_e, adj_r, ent, rel, W, bias, out);
}